// round 1
// baseline (speedup 1.0000x reference)
#include <cuda_runtime.h>
#include <math.h>

#define BATCH 2048
#define HDIM  1024
#define G3    3072
#define NMSG  4096

// ---------------- scratch (static device globals; no allocation) ----------------
__device__ float g_Hin[7LL * BATCH * HDIM];     // per-receiver message accumulators
__device__ float g_Hv[(long)BATCH * HDIM];      // current node hidden
__device__ float g_gi[(long)BATCH * G3];        // input-gate preactivations
__device__ float g_gh[(long)BATCH * G3];        // hidden-gate preactivations
__device__ float g_msg[(long)BATCH * NMSG];     // [A|B|C|D] sender projections
__device__ float g_Wt[3 * 32 * G3];             // transposed x-weights (padded K=32)
__device__ float g_Wmsg[(long)NMSG * HDIM];     // packed [Wg1;Wg2;Wm1;Wm2]

__device__ __forceinline__ float sigmoidf(float x) { return 1.f / (1.f + expf(-x)); }
__device__ __forceinline__ float softplusf(float x) {
    return (x > 20.f) ? x : log1pf(expf(x));
}

// ---------------- weight packing ----------------
// Wt[k*3072 + j] = W[j*K + k]  (k < K, padded with zeros to 32)
__global__ void pack_xw(const float* __restrict__ W, float* __restrict__ Wt, int K) {
    int idx = blockIdx.x * blockDim.x + threadIdx.x;
    if (idx >= 32 * G3) return;
    int kk = idx / G3, j = idx - kk * G3;
    Wt[idx] = (kk < K) ? W[j * K + kk] : 0.f;
}

// P[4096][1024] = rows: Wg[:, :1024], Wg[:, 1024:], Wm[:, :1024], Wm[:, 1024:]
__global__ void pack_msgw(const float* __restrict__ Wg, const float* __restrict__ Wm,
                          float* __restrict__ P) {
    int idx = blockIdx.x * blockDim.x + threadIdx.x;   // 4096*1024 total
    int j = idx >> 10, k = idx & 1023;
    float v;
    if (j < 1024)       v = Wg[j * 2048 + k];
    else if (j < 2048)  v = Wg[(j - 1024) * 2048 + 1024 + k];
    else if (j < 3072)  v = Wm[(j - 2048) * 2048 + k];
    else                v = Wm[(j - 3072) * 2048 + 1024 + k];
    P[idx] = v;
}

// ---------------- small-K input matmul: gi = (mask? X : 0) @ Wihᵀ + bih ----------------
// out[b, 0:3072], Wt transposed [32][3072]
__global__ __launch_bounds__(256) void gemm_x(
    const float* __restrict__ X, int ldx, int K,
    const float* __restrict__ Wt, const float* __restrict__ bias,
    float* __restrict__ out, const int* __restrict__ mask, int mstride)
{
    __shared__ float xs[32];
    int b = blockIdx.y;
    int j = blockIdx.x * 256 + threadIdx.x;
    if (threadIdx.x < 32) {
        float v = (threadIdx.x < K) ? X[(long)b * ldx + threadIdx.x] : 0.f;
        if (mask && !(mask[(long)b * mstride] > 0)) v = 0.f;
        xs[threadIdx.x] = v;
    }
    __syncthreads();
    float acc = 0.f;
    for (int k = 0; k < K; k++) acc += xs[k] * Wt[k * G3 + j];
    out[(long)b * G3 + j] = acc + bias[j];
}

// ---------------- GRU elementwise combine ----------------
__global__ __launch_bounds__(256) void gru_combine(
    const float* __restrict__ gi, const float* __restrict__ gh,
    const float* __restrict__ hp, float* __restrict__ ho)
{
    int idx = blockIdx.x * 256 + threadIdx.x;       // BATCH*HDIM
    int b = idx >> 10, h = idx & 1023;
    long base = (long)b * G3 + h;
    float ir = gi[base], iz = gi[base + 1024], in_ = gi[base + 2048];
    float hr = gh[base], hz = gh[base + 1024], hn = gh[base + 2048];
    float r = sigmoidf(ir + hr);
    float z = sigmoidf(iz + hz);
    float n = tanhf(in_ + r * hn);
    ho[idx] = (1.f - z) * n + z * hp[idx];
}

// ---------------- message push: sender S -> receivers u < S ----------------
__global__ __launch_bounds__(256) void msg_scatter(
    const float* __restrict__ Mg, const int* __restrict__ adj,
    const float* __restrict__ bg, float* __restrict__ HinBase, int S)
{
    int u = blockIdx.y;
    int idx = blockIdx.x * 256 + threadIdx.x;       // BATCH*HDIM
    int b = idx >> 10, h = idx & 1023;
    float fp = (adj[(long)b * 49 + S * 7 + u] > 0) ? 1.f : 0.f;
    float fs = (adj[(long)b * 49 + u * 7 + S] > 0) ? 1.f : 0.f;
    const float* M = Mg + (long)b * NMSG;
    float g = sigmoidf(fp * M[h] + fs * M[1024 + h] + bg[h]);
    float m = fp * M[2048 + h] + fs * M[3072 + h];
    HinBase[(long)u * BATCH * HDIM + idx] += g * m;
}

// ---------------- main SGEMM: C[M,N] = A[M,K] * B[N,K]^T (+bias, +act) ----------------
// M = 2048 always; N,K multiples of 128/16. Double-buffered smem, 8x8 microtiles.
#define BM 128
#define BN 128
#define BK 16
#define PAD 4

__global__ __launch_bounds__(256) void sgemm_nt(
    const float* __restrict__ A, const float* __restrict__ B,
    const float* __restrict__ bias, float* __restrict__ C,
    int N, int K, int act)
{
    __shared__ float As[2][BK][BM + PAD];
    __shared__ float Bs[2][BK][BN + PAD];
    const int tid = threadIdx.x;
    const int bm = blockIdx.y * BM;
    const int bn = blockIdx.x * BN;
    const int lrow = tid >> 2;             // 0..63
    const int lcol = (tid & 3) << 2;       // 0,4,8,12
    const float* Aptr = A + (long)(bm + lrow) * K + lcol;
    const float* Bptr = B + (long)(bn + lrow) * K + lcol;

    float acc[8][8];
#pragma unroll
    for (int i = 0; i < 8; i++)
#pragma unroll
        for (int j = 0; j < 8; j++) acc[i][j] = 0.f;

    // preload tile 0
    {
#pragma unroll
        for (int r = 0; r < BM; r += 64) {
            float4 va = *(const float4*)(Aptr + (long)r * K);
            As[0][lcol + 0][lrow + r] = va.x; As[0][lcol + 1][lrow + r] = va.y;
            As[0][lcol + 2][lrow + r] = va.z; As[0][lcol + 3][lrow + r] = va.w;
            float4 vb = *(const float4*)(Bptr + (long)r * K);
            Bs[0][lcol + 0][lrow + r] = vb.x; Bs[0][lcol + 1][lrow + r] = vb.y;
            Bs[0][lcol + 2][lrow + r] = vb.z; Bs[0][lcol + 3][lrow + r] = vb.w;
        }
    }
    __syncthreads();

    const int tx = tid & 15, ty = tid >> 4;
    const int nt = K / BK;
    float4 pa[2], pb[2];

    for (int t = 0; t < nt; t++) {
        const int cur = t & 1, nxt = cur ^ 1;
        const bool more = (t + 1 < nt);
        if (more) {
            int koff = (t + 1) * BK;
#pragma unroll
            for (int r = 0; r < 2; r++) {
                pa[r] = *(const float4*)(Aptr + (long)(r * 64) * K + koff);
                pb[r] = *(const float4*)(Bptr + (long)(r * 64) * K + koff);
            }
        }
#pragma unroll
        for (int k = 0; k < BK; k++) {
            float a[8], b[8];
            *(float4*)(a)     = *(const float4*)&As[cur][k][ty * 8];
            *(float4*)(a + 4) = *(const float4*)&As[cur][k][ty * 8 + 4];
            *(float4*)(b)     = *(const float4*)&Bs[cur][k][tx * 8];
            *(float4*)(b + 4) = *(const float4*)&Bs[cur][k][tx * 8 + 4];
#pragma unroll
            for (int i = 0; i < 8; i++)
#pragma unroll
                for (int j = 0; j < 8; j++)
                    acc[i][j] += a[i] * b[j];
        }
        if (more) {
#pragma unroll
            for (int r = 0; r < 2; r++) {
                int rr = r * 64;
                As[nxt][lcol + 0][lrow + rr] = pa[r].x; As[nxt][lcol + 1][lrow + rr] = pa[r].y;
                As[nxt][lcol + 2][lrow + rr] = pa[r].z; As[nxt][lcol + 3][lrow + rr] = pa[r].w;
                Bs[nxt][lcol + 0][lrow + rr] = pb[r].x; Bs[nxt][lcol + 1][lrow + rr] = pb[r].y;
                Bs[nxt][lcol + 2][lrow + rr] = pb[r].z; Bs[nxt][lcol + 3][lrow + rr] = pb[r].w;
            }
        }
        __syncthreads();
    }

#pragma unroll
    for (int i = 0; i < 8; i++) {
        long row = bm + ty * 8 + i;
#pragma unroll
        for (int j0 = 0; j0 < 8; j0 += 4) {
            int col = bn + tx * 8 + j0;
            float4 v;
            v.x = acc[i][j0 + 0] + (bias ? bias[col + 0] : 0.f);
            v.y = acc[i][j0 + 1] + (bias ? bias[col + 1] : 0.f);
            v.z = acc[i][j0 + 2] + (bias ? bias[col + 2] : 0.f);
            v.w = acc[i][j0 + 3] + (bias ? bias[col + 3] : 0.f);
            if (act == 1) {
                v.x = softplusf(v.x); v.y = softplusf(v.y);
                v.z = softplusf(v.z); v.w = softplusf(v.w);
            }
            *(float4*)(C + row * N + col) = v;
        }
    }
}

// ---------------- orchestration ----------------
extern "C" void kernel_launch(void* const* d_in, const int* in_sizes, int n_in,
                              void* d_out, int out_size)
{
    const float* X      = (const float*)d_in[0];
    const int*   adj    = (const int*)  d_in[1];
    const float* W_ih_c = (const float*)d_in[2];
    const float* W_hh_c = (const float*)d_in[3];
    const float* b_ih_c = (const float*)d_in[4];
    const float* b_hh_c = (const float*)d_in[5];
    const float* W_ih_l = (const float*)d_in[6];
    const float* W_hh_l = (const float*)d_in[7];
    const float* b_ih_l = (const float*)d_in[8];
    const float* b_hh_l = (const float*)d_in[9];
    const float* W_ih_r = (const float*)d_in[10];
    const float* W_hh_r = (const float*)d_in[11];
    const float* b_ih_r = (const float*)d_in[12];
    const float* b_hh_r = (const float*)d_in[13];
    const float* Wg     = (const float*)d_in[14];
    const float* bg     = (const float*)d_in[15];
    const float* Wm     = (const float*)d_in[16];
    const float* Wmu    = (const float*)d_in[17];
    const float* bmu    = (const float*)d_in[18];
    const float* Wstd   = (const float*)d_in[19];
    const float* bstd   = (const float*)d_in[20];

    float *Hin, *Hv, *gi, *gh, *msg, *Wt, *Wmsg;
    cudaGetSymbolAddress((void**)&Hin,  g_Hin);
    cudaGetSymbolAddress((void**)&Hv,   g_Hv);
    cudaGetSymbolAddress((void**)&gi,   g_gi);
    cudaGetSymbolAddress((void**)&gh,   g_gh);
    cudaGetSymbolAddress((void**)&msg,  g_msg);
    cudaGetSymbolAddress((void**)&Wt,   g_Wt);
    cudaGetSymbolAddress((void**)&Wmsg, g_Wmsg);

    cudaMemsetAsync(Hin, 0, sizeof(float) * 7LL * BATCH * HDIM, 0);

    const int PK = (32 * G3 + 255) / 256;
    pack_xw<<<PK, 256>>>(W_ih_c, Wt,                27);
    pack_xw<<<PK, 256>>>(W_ih_l, Wt + 32 * G3,      27);
    pack_xw<<<PK, 256>>>(W_ih_r, Wt + 2 * 32 * G3,  23);
    pack_msgw<<<(NMSG * HDIM) / 256, 256>>>(Wg, Wm, Wmsg);

    dim3 gGI(G3 / 256, BATCH);                 // (12, 2048)
    dim3 gGH(G3 / BN, BATCH / BM);             // (24, 16)
    dim3 gMS(NMSG / BN, BATCH / BM);           // (32, 16)
    dim3 gOUT(256 / BN, BATCH / BM);           // (2, 16)
    const int EW = (BATCH * HDIM) / 256;       // 8192

    for (int v = 6; v >= 0; v--) {
        float* Hin_v = Hin + (long)v * BATCH * HDIM;
        const float* Wt_x = (v == 0) ? (Wt + 2 * 32 * G3) : Wt;
        int Kx            = (v == 0) ? 23 : 27;
        const float* bih  = (v == 0) ? b_ih_r : b_ih_c;
        const float* Whh  = (v == 0) ? W_hh_r : W_hh_c;
        const float* bhh  = (v == 0) ? b_hh_r : b_hh_c;

        // GRU 1
        gemm_x<<<gGI, 256>>>(X + v * 27, 7 * 27, Kx, Wt_x, bih, gi, nullptr, 0);
        sgemm_nt<<<gGH, 256>>>(Hin_v, Whh, bhh, gh, G3, HDIM, 0);
        gru_combine<<<EW, 256>>>(gi, gh, Hin_v, Hv);

        if (v > 0) {
            // GRU 2 (self-loop), X masked by adj[b,v,v]
            gemm_x<<<gGI, 256>>>(X + v * 27, 7 * 27, 27, Wt + 32 * G3, b_ih_l,
                                 gi, adj + 8 * v, 49);
            sgemm_nt<<<gGH, 256>>>(Hv, W_hh_l, b_hh_l, gh, G3, HDIM, 0);
            gru_combine<<<EW, 256>>>(gi, gh, Hv, Hv);

            // sender projections A|B|C|D, then push to all receivers u < v
            sgemm_nt<<<gMS, 256>>>(Hv, Wmsg, nullptr, msg, NMSG, HDIM, 0);
            msg_scatter<<<dim3(EW, v), 256>>>(msg, adj, bg, Hin, v);
        }
    }

    float* out = (float*)d_out;
    sgemm_nt<<<gOUT, 256>>>(Hv, Wmu,  bmu,  out,                 256, HDIM, 0);
    sgemm_nt<<<gOUT, 256>>>(Hv, Wstd, bstd, out + BATCH * 256,   256, HDIM, 1);
}

// round 3
// speedup vs baseline: 2.2675x; 2.2675x over previous
#include <cuda_runtime.h>
#include <math.h>

#define BATCH 2048
#define HDIM  1024
#define G3    3072
#define NMSG  4096

// ---------------- scratch (static device globals; no allocation) ----------------
__device__ float g_Hin[7LL * BATCH * HDIM];     // per-receiver message accumulators
__device__ float g_Hv[(long)BATCH * HDIM];      // current node hidden
__device__ float g_gi[(long)BATCH * G3];        // input-gate preactivations
__device__ float g_gh[(long)BATCH * G3];        // hidden-gate preactivations
__device__ float g_msg[(long)BATCH * NMSG];     // [A|B|C|D] sender projections
__device__ float g_Wt[3 * 32 * G3];             // transposed x-weights (padded K=32)
__device__ float g_Wmsg[(long)NMSG * HDIM];     // packed [Wg1;Wg2;Wm1;Wm2]

__device__ __forceinline__ float sigmoidf(float x) { return 1.f / (1.f + expf(-x)); }
__device__ __forceinline__ float softplusf(float x) {
    return (x > 20.f) ? x : log1pf(expf(x));
}
__device__ __forceinline__ unsigned f2tf(float f) {
    unsigned u;
    asm("cvt.rna.tf32.f32 %0, %1;" : "=r"(u) : "f"(f));
    return u;
}

// ---------------- weight packing ----------------
__global__ void pack_xw(const float* __restrict__ W, float* __restrict__ Wt, int K) {
    int idx = blockIdx.x * blockDim.x + threadIdx.x;
    if (idx >= 32 * G3) return;
    int kk = idx / G3, j = idx - kk * G3;
    Wt[idx] = (kk < K) ? W[j * K + kk] : 0.f;
}

__global__ void pack_msgw(const float* __restrict__ Wg, const float* __restrict__ Wm,
                          float* __restrict__ P) {
    int idx = blockIdx.x * blockDim.x + threadIdx.x;
    int j = idx >> 10, k = idx & 1023;
    float v;
    if (j < 1024)       v = Wg[j * 2048 + k];
    else if (j < 2048)  v = Wg[(j - 1024) * 2048 + 1024 + k];
    else if (j < 3072)  v = Wm[(j - 2048) * 2048 + k];
    else                v = Wm[(j - 3072) * 2048 + 1024 + k];
    P[idx] = v;
}

// ---------------- small-K input matmul ----------------
__global__ __launch_bounds__(256) void gemm_x(
    const float* __restrict__ X, int ldx, int K,
    const float* __restrict__ Wt, const float* __restrict__ bias,
    float* __restrict__ out, const int* __restrict__ mask, int mstride)
{
    __shared__ float xs[32];
    int b = blockIdx.y;
    int j = blockIdx.x * 256 + threadIdx.x;
    if (threadIdx.x < 32) {
        float v = (threadIdx.x < K) ? X[(long)b * ldx + threadIdx.x] : 0.f;
        if (mask && !(mask[(long)b * mstride] > 0)) v = 0.f;
        xs[threadIdx.x] = v;
    }
    __syncthreads();
    float acc = 0.f;
    for (int k = 0; k < K; k++) acc += xs[k] * Wt[k * G3 + j];
    out[(long)b * G3 + j] = acc + bias[j];
}

// ---------------- GRU elementwise combine ----------------
__global__ __launch_bounds__(256) void gru_combine(
    const float* __restrict__ gi, const float* __restrict__ gh,
    const float* __restrict__ hp, float* __restrict__ ho)
{
    int idx = blockIdx.x * 256 + threadIdx.x;
    int b = idx >> 10, h = idx & 1023;
    long base = (long)b * G3 + h;
    float ir = gi[base], iz = gi[base + 1024], in_ = gi[base + 2048];
    float hr = gh[base], hz = gh[base + 1024], hn = gh[base + 2048];
    float r = sigmoidf(ir + hr);
    float z = sigmoidf(iz + hz);
    float n = tanhf(in_ + r * hn);
    ho[idx] = (1.f - z) * n + z * hp[idx];
}

// ---------------- message push: sender S -> all receivers u < S, fused ----------------
__global__ __launch_bounds__(256) void msg_scatter_all(
    const float* __restrict__ Mg, const int* __restrict__ adj,
    const float* __restrict__ bg, float* __restrict__ HinBase, int S)
{
    int idx = blockIdx.x * 256 + threadIdx.x;       // BATCH*HDIM
    int b = idx >> 10, h = idx & 1023;
    const float* M = Mg + (long)b * NMSG;
    float Av = M[h], Bv = M[1024 + h], Cv = M[2048 + h], Dv = M[3072 + h];
    float bgh = bg[h];
    for (int u = 0; u < S; u++) {
        float fp = (adj[(long)b * 49 + S * 7 + u] > 0) ? 1.f : 0.f;
        float fs = (adj[(long)b * 49 + u * 7 + S] > 0) ? 1.f : 0.f;
        float g = sigmoidf(fp * Av + fs * Bv + bgh);
        float m = fp * Cv + fs * Dv;
        HinBase[(long)u * BATCH * HDIM + idx] += g * m;
    }
}

// ---------------- TF32 tensor-core GEMM: C[M,N] = A[M,K] * B[N,K]^T (+bias,+act) ----
// BM=128, BN=128, BK=16. 256 threads, 8 warps in 4x2; warp tile 32x64.
#define BM 128
#define BN 128
#define BK 16
#define KS 20   // padded k-stride in smem words (conflict-free: 20m mod 32 distinct)

__global__ __launch_bounds__(256) void tgemm_nt(
    const float* __restrict__ A, const float* __restrict__ B,
    const float* __restrict__ bias, float* __restrict__ C,
    int N, int K, int act)
{
    __shared__ unsigned As[2][BM][KS];
    __shared__ unsigned Bs[2][BN][KS];

    const int tid  = threadIdx.x;
    const int lane = tid & 31;
    const int warp = tid >> 5;
    const int wm   = warp >> 1;           // 0..3  (rows, 32 each)
    const int wn   = warp & 1;            // 0..1  (cols, 64 each)
    const int bm   = blockIdx.y * BM;
    const int bn   = blockIdx.x * BN;

    const int lrow = tid >> 2;            // 0..63
    const int lcol = (tid & 3) << 2;      // 0,4,8,12
    const float* Aptr = A + (long)(bm + lrow) * K + lcol;
    const float* Bptr = B + (long)(bn + lrow) * K + lcol;

    float acc[2][8][4];
#pragma unroll
    for (int i = 0; i < 2; i++)
#pragma unroll
        for (int j = 0; j < 8; j++)
#pragma unroll
            for (int q = 0; q < 4; q++) acc[i][j][q] = 0.f;

    // preload tile 0
    {
#pragma unroll
        for (int r = 0; r < 2; r++) {
            float4 va = *(const float4*)(Aptr + (long)(r * 64) * K);
            unsigned* da = &As[0][lrow + r * 64][lcol];
            da[0] = f2tf(va.x); da[1] = f2tf(va.y); da[2] = f2tf(va.z); da[3] = f2tf(va.w);
            float4 vb = *(const float4*)(Bptr + (long)(r * 64) * K);
            unsigned* db = &Bs[0][lrow + r * 64][lcol];
            db[0] = f2tf(vb.x); db[1] = f2tf(vb.y); db[2] = f2tf(vb.z); db[3] = f2tf(vb.w);
        }
    }
    __syncthreads();

    const int nt = K / BK;
    const int gr = lane >> 2;             // 0..7
    const int gk = lane & 3;              // 0..3
    float4 pa[2], pb[2];

    for (int t = 0; t < nt; t++) {
        const int cur = t & 1, nxt = cur ^ 1;
        const bool more = (t + 1 < nt);
        if (more) {
            int koff = (t + 1) * BK;
#pragma unroll
            for (int r = 0; r < 2; r++) {
                pa[r] = *(const float4*)(Aptr + (long)(r * 64) * K + koff);
                pb[r] = *(const float4*)(Bptr + (long)(r * 64) * K + koff);
            }
        }
#pragma unroll
        for (int k8 = 0; k8 < 2; k8++) {
            const int kb = k8 * 8;
            unsigned a[2][4], b[8][2];
#pragma unroll
            for (int mt = 0; mt < 2; mt++) {
                int m = wm * 32 + mt * 16 + gr;
                a[mt][0] = As[cur][m][kb + gk];
                a[mt][1] = As[cur][m + 8][kb + gk];
                a[mt][2] = As[cur][m][kb + gk + 4];
                a[mt][3] = As[cur][m + 8][kb + gk + 4];
            }
#pragma unroll
            for (int ntile = 0; ntile < 8; ntile++) {
                int n = wn * 64 + ntile * 8 + gr;
                b[ntile][0] = Bs[cur][n][kb + gk];
                b[ntile][1] = Bs[cur][n][kb + gk + 4];
            }
#pragma unroll
            for (int mt = 0; mt < 2; mt++)
#pragma unroll
                for (int ntile = 0; ntile < 8; ntile++) {
                    asm volatile(
                        "mma.sync.aligned.m16n8k8.row.col.f32.tf32.tf32.f32 "
                        "{%0,%1,%2,%3}, {%4,%5,%6,%7}, {%8,%9}, {%0,%1,%2,%3};\n"
                        : "+f"(acc[mt][ntile][0]), "+f"(acc[mt][ntile][1]),
                          "+f"(acc[mt][ntile][2]), "+f"(acc[mt][ntile][3])
                        : "r"(a[mt][0]), "r"(a[mt][1]), "r"(a[mt][2]), "r"(a[mt][3]),
                          "r"(b[ntile][0]), "r"(b[ntile][1]));
                }
        }
        if (more) {
#pragma unroll
            for (int r = 0; r < 2; r++) {
                unsigned* da = &As[nxt][lrow + r * 64][lcol];
                da[0] = f2tf(pa[r].x); da[1] = f2tf(pa[r].y);
                da[2] = f2tf(pa[r].z); da[3] = f2tf(pa[r].w);
                unsigned* db = &Bs[nxt][lrow + r * 64][lcol];
                db[0] = f2tf(pb[r].x); db[1] = f2tf(pb[r].y);
                db[2] = f2tf(pb[r].z); db[3] = f2tf(pb[r].w);
            }
        }
        __syncthreads();
    }

    // epilogue
    const int gc2 = (lane & 3) * 2;
#pragma unroll
    for (int mt = 0; mt < 2; mt++) {
        long row0 = bm + wm * 32 + mt * 16 + gr;
#pragma unroll
        for (int ntile = 0; ntile < 8; ntile++) {
            int col = bn + wn * 64 + ntile * 8 + gc2;
            float b0 = bias ? bias[col] : 0.f;
            float b1 = bias ? bias[col + 1] : 0.f;
            float2 v0, v1;
            v0.x = acc[mt][ntile][0] + b0; v0.y = acc[mt][ntile][1] + b1;
            v1.x = acc[mt][ntile][2] + b0; v1.y = acc[mt][ntile][3] + b1;
            if (act == 1) {
                v0.x = softplusf(v0.x); v0.y = softplusf(v0.y);
                v1.x = softplusf(v1.x); v1.y = softplusf(v1.y);
            }
            *(float2*)(C + row0 * N + col)       = v0;
            *(float2*)(C + (row0 + 8) * N + col) = v1;
        }
    }
}

// ---------------- orchestration ----------------
extern "C" void kernel_launch(void* const* d_in, const int* in_sizes, int n_in,
                              void* d_out, int out_size)
{
    const float* X      = (const float*)d_in[0];
    const int*   adj    = (const int*)  d_in[1];
    const float* W_ih_c = (const float*)d_in[2];
    const float* W_hh_c = (const float*)d_in[3];
    const float* b_ih_c = (const float*)d_in[4];
    const float* b_hh_c = (const float*)d_in[5];
    const float* W_ih_l = (const float*)d_in[6];
    const float* W_hh_l = (const float*)d_in[7];
    const float* b_ih_l = (const float*)d_in[8];
    const float* b_hh_l = (const float*)d_in[9];
    const float* W_ih_r = (const float*)d_in[10];
    const float* W_hh_r = (const float*)d_in[11];
    const float* b_ih_r = (const float*)d_in[12];
    const float* b_hh_r = (const float*)d_in[13];
    const float* Wg     = (const float*)d_in[14];
    const float* bg     = (const float*)d_in[15];
    const float* Wm     = (const float*)d_in[16];
    const float* Wmu    = (const float*)d_in[17];
    const float* bmu    = (const float*)d_in[18];
    const float* Wstd   = (const float*)d_in[19];
    const float* bstd   = (const float*)d_in[20];

    float *Hin, *Hv, *gi, *gh, *msg, *Wt, *Wmsg;
    cudaGetSymbolAddress((void**)&Hin,  g_Hin);
    cudaGetSymbolAddress((void**)&Hv,   g_Hv);
    cudaGetSymbolAddress((void**)&gi,   g_gi);
    cudaGetSymbolAddress((void**)&gh,   g_gh);
    cudaGetSymbolAddress((void**)&msg,  g_msg);
    cudaGetSymbolAddress((void**)&Wt,   g_Wt);
    cudaGetSymbolAddress((void**)&Wmsg, g_Wmsg);

    cudaMemsetAsync(Hin, 0, sizeof(float) * 7LL * BATCH * HDIM, 0);

    const int PK = (32 * G3 + 255) / 256;
    pack_xw<<<PK, 256>>>(W_ih_c, Wt,                27);
    pack_xw<<<PK, 256>>>(W_ih_l, Wt + 32 * G3,      27);
    pack_xw<<<PK, 256>>>(W_ih_r, Wt + 2 * 32 * G3,  23);
    pack_msgw<<<(NMSG * HDIM) / 256, 256>>>(Wg, Wm, Wmsg);

    dim3 gGI(G3 / 256, BATCH);                 // (12, 2048)
    dim3 gGH(G3 / BN, BATCH / BM);             // (24, 16)
    dim3 gMS(NMSG / BN, BATCH / BM);           // (32, 16)
    dim3 gOUT(256 / BN, BATCH / BM);           // (2, 16)
    const int EW = (BATCH * HDIM) / 256;       // 8192

    for (int v = 6; v >= 0; v--) {
        float* Hin_v = Hin + (long)v * BATCH * HDIM;
        const float* Wt_x = (v == 0) ? (Wt + 2 * 32 * G3) : Wt;
        int Kx            = (v == 0) ? 23 : 27;
        const float* bih  = (v == 0) ? b_ih_r : b_ih_c;
        const float* Whh  = (v == 0) ? W_hh_r : W_hh_c;
        const float* bhh  = (v == 0) ? b_hh_r : b_hh_c;

        // GRU 1
        gemm_x<<<gGI, 256>>>(X + v * 27, 7 * 27, Kx, Wt_x, bih, gi, nullptr, 0);
        tgemm_nt<<<gGH, 256>>>(Hin_v, Whh, bhh, gh, G3, HDIM, 0);
        gru_combine<<<EW, 256>>>(gi, gh, Hin_v, Hv);

        if (v > 0) {
            // GRU 2 (self-loop), X masked by adj[b,v,v]
            gemm_x<<<gGI, 256>>>(X + v * 27, 7 * 27, 27, Wt + 32 * G3, b_ih_l,
                                 gi, adj + 8 * v, 49);
            tgemm_nt<<<gGH, 256>>>(Hv, W_hh_l, b_hh_l, gh, G3, HDIM, 0);
            gru_combine<<<EW, 256>>>(gi, gh, Hv, Hv);

            // sender projections A|B|C|D, then push to all receivers u < v
            tgemm_nt<<<gMS, 256>>>(Hv, Wmsg, nullptr, msg, NMSG, HDIM, 0);
            msg_scatter_all<<<EW, 256>>>(msg, adj, bg, Hin, v);
        }
    }

    float* out = (float*)d_out;
    tgemm_nt<<<gOUT, 256>>>(Hv, Wmu,  bmu,  out,               256, HDIM, 0);
    tgemm_nt<<<gOUT, 256>>>(Hv, Wstd, bstd, out + BATCH * 256, 256, HDIM, 1);
}

// round 4
// speedup vs baseline: 2.6110x; 1.1515x over previous
#include <cuda_runtime.h>
#include <math.h>

#define BATCH 2048
#define HDIM  1024
#define G3    3072
#define NMSG  4096

// ---------------- scratch (static device globals; no allocation) ----------------
__device__ float g_Hin[7LL * BATCH * HDIM];       // per-receiver message accumulators
__device__ float g_Hv[(long)BATCH * HDIM];        // current node hidden
__device__ float g_gh[(long)BATCH * G3];          // hidden-gate preactivations
__device__ float g_msg[(long)BATCH * NMSG];       // [A|B|C|D] sender projections
__device__ float g_giAll[13LL * BATCH * G3];      // all input-gate preactivations
__device__ float g_Xpad[13LL * BATCH * 32];       // packed/padded X slices
__device__ float g_Wx32[3LL * G3 * 32];           // x-weights padded to K=32 [N,K]
__device__ float g_Wmsg[(long)NMSG * HDIM];       // packed [Wg1;Wg2;Wm1;Wm2]

__device__ __forceinline__ float sigmoidf(float x) { return 1.f / (1.f + expf(-x)); }
__device__ __forceinline__ float softplusf(float x) {
    return (x > 20.f) ? x : log1pf(expf(x));
}
__device__ __forceinline__ unsigned f2tf(float f) {
    unsigned u;
    asm("cvt.rna.tf32.f32 %0, %1;" : "=r"(u) : "f"(f));
    return u;
}

// ---------------- packing ----------------
// Xpad slots: [0..5] = X node v=1..6 ; [6..11] = masked X node v=1..6 ; [12] = X0[:23]
__global__ void pack_xpad(const float* __restrict__ X, const int* __restrict__ adj,
                          float* __restrict__ Xp) {
    int idx = blockIdx.x * blockDim.x + threadIdx.x;   // 13*2048*32
    if (idx >= 13 * BATCH * 32) return;
    int slot = idx / (BATCH * 32);
    int rem  = idx - slot * (BATCH * 32);
    int b = rem >> 5, k = rem & 31;
    float v = 0.f;
    if (slot < 6) {
        int node = slot + 1;
        if (k < 27) v = X[(long)b * 189 + node * 27 + k];
    } else if (slot < 12) {
        int node = slot - 5;
        if (k < 27 && adj[(long)b * 49 + node * 8] > 0)
            v = X[(long)b * 189 + node * 27 + k];
    } else {
        if (k < 23) v = X[(long)b * 189 + k];
    }
    Xp[idx] = v;
}

// B-side [N=3072, K=32] zero-padded
__global__ void pack_wx32(const float* __restrict__ W, float* __restrict__ P, int K) {
    int idx = blockIdx.x * blockDim.x + threadIdx.x;   // 3072*32
    if (idx >= G3 * 32) return;
    int j = idx >> 5, k = idx & 31;
    P[idx] = (k < K) ? W[j * K + k] : 0.f;
}

__global__ void pack_msgw(const float* __restrict__ Wg, const float* __restrict__ Wm,
                          float* __restrict__ P) {
    int idx = blockIdx.x * blockDim.x + threadIdx.x;
    int j = idx >> 10, k = idx & 1023;
    float v;
    if (j < 1024)       v = Wg[j * 2048 + k];
    else if (j < 2048)  v = Wg[(j - 1024) * 2048 + 1024 + k];
    else if (j < 3072)  v = Wm[(j - 2048) * 2048 + k];
    else                v = Wm[(j - 3072) * 2048 + 1024 + k];
    P[idx] = v;
}

// ---------------- GRU elementwise combine ----------------
__global__ __launch_bounds__(256) void gru_combine(
    const float* __restrict__ gi, const float* __restrict__ gh,
    const float* __restrict__ hp, float* __restrict__ ho)
{
    int idx = blockIdx.x * 256 + threadIdx.x;
    int b = idx >> 10, h = idx & 1023;
    long base = (long)b * G3 + h;
    float ir = gi[base], iz = gi[base + 1024], in_ = gi[base + 2048];
    float hr = gh[base], hz = gh[base + 1024], hn = gh[base + 2048];
    float r = sigmoidf(ir + hr);
    float z = sigmoidf(iz + hz);
    float n = tanhf(in_ + r * hn);
    ho[idx] = (1.f - z) * n + z * hp[idx];
}

// ---------------- message push: sender S -> all receivers u < S, fused ----------------
__global__ __launch_bounds__(256) void msg_scatter_all(
    const float* __restrict__ Mg, const int* __restrict__ adj,
    const float* __restrict__ bg, float* __restrict__ HinBase, int S)
{
    int idx = blockIdx.x * 256 + threadIdx.x;       // BATCH*HDIM
    int b = idx >> 10, h = idx & 1023;
    const float* M = Mg + (long)b * NMSG;
    float Av = M[h], Bv = M[1024 + h], Cv = M[2048 + h], Dv = M[3072 + h];
    float bgh = bg[h];
    for (int u = 0; u < S; u++) {
        float fp = (adj[(long)b * 49 + S * 7 + u] > 0) ? 1.f : 0.f;
        float fs = (adj[(long)b * 49 + u * 7 + S] > 0) ? 1.f : 0.f;
        float g = sigmoidf(fp * Av + fs * Bv + bgh);
        float m = fp * Cv + fs * Dv;
        HinBase[(long)u * BATCH * HDIM + idx] += g * m;
    }
}

// ---------------- TF32 tensor-core GEMM: C[M,N] = A[M,K] * B[N,K]^T (+bias,+act) ----
#define BM 128
#define BN 128
#define BK 16
#define KS 20   // padded k-stride in smem words

__global__ __launch_bounds__(256, 2) void tgemm_nt(
    const float* __restrict__ A, const float* __restrict__ B,
    const float* __restrict__ bias, float* __restrict__ C,
    int N, int K, int act)
{
    __shared__ unsigned As[2][BM][KS];
    __shared__ unsigned Bs[2][BN][KS];

    const int tid  = threadIdx.x;
    const int lane = tid & 31;
    const int warp = tid >> 5;
    const int wm   = warp >> 1;           // 0..3  (rows, 32 each)
    const int wn   = warp & 1;            // 0..1  (cols, 64 each)
    const int bm   = blockIdx.y * BM;
    const int bn   = blockIdx.x * BN;

    const int lrow = tid >> 2;            // 0..63
    const int lcol = (tid & 3) << 2;      // 0,4,8,12
    const float* Aptr = A + (long)(bm + lrow) * K + lcol;
    const float* Bptr = B + (long)(bn + lrow) * K + lcol;

    float acc[2][8][4];
#pragma unroll
    for (int i = 0; i < 2; i++)
#pragma unroll
        for (int j = 0; j < 8; j++)
#pragma unroll
            for (int q = 0; q < 4; q++) acc[i][j][q] = 0.f;

    // preload tile 0
    {
#pragma unroll
        for (int r = 0; r < 2; r++) {
            float4 va = *(const float4*)(Aptr + (long)(r * 64) * K);
            uint4 ua = { f2tf(va.x), f2tf(va.y), f2tf(va.z), f2tf(va.w) };
            *(uint4*)&As[0][lrow + r * 64][lcol] = ua;
            float4 vb = *(const float4*)(Bptr + (long)(r * 64) * K);
            uint4 ub = { f2tf(vb.x), f2tf(vb.y), f2tf(vb.z), f2tf(vb.w) };
            *(uint4*)&Bs[0][lrow + r * 64][lcol] = ub;
        }
    }
    __syncthreads();

    const int nt = K / BK;
    const int gr = lane >> 2;             // 0..7
    const int gk = lane & 3;              // 0..3
    float4 pa[2], pb[2];

    for (int t = 0; t < nt; t++) {
        const int cur = t & 1, nxt = cur ^ 1;
        const bool more = (t + 1 < nt);
        if (more) {
            int koff = (t + 1) * BK;
#pragma unroll
            for (int r = 0; r < 2; r++) {
                pa[r] = *(const float4*)(Aptr + (long)(r * 64) * K + koff);
                pb[r] = *(const float4*)(Bptr + (long)(r * 64) * K + koff);
            }
        }
#pragma unroll
        for (int k8 = 0; k8 < 2; k8++) {
            const int kb = k8 * 8;
            unsigned a[2][4], b[8][2];
#pragma unroll
            for (int mt = 0; mt < 2; mt++) {
                int m = wm * 32 + mt * 16 + gr;
                a[mt][0] = As[cur][m][kb + gk];
                a[mt][1] = As[cur][m + 8][kb + gk];
                a[mt][2] = As[cur][m][kb + gk + 4];
                a[mt][3] = As[cur][m + 8][kb + gk + 4];
            }
#pragma unroll
            for (int ntile = 0; ntile < 8; ntile++) {
                int n = wn * 64 + ntile * 8 + gr;
                b[ntile][0] = Bs[cur][n][kb + gk];
                b[ntile][1] = Bs[cur][n][kb + gk + 4];
            }
#pragma unroll
            for (int mt = 0; mt < 2; mt++)
#pragma unroll
                for (int ntile = 0; ntile < 8; ntile++) {
                    asm volatile(
                        "mma.sync.aligned.m16n8k8.row.col.f32.tf32.tf32.f32 "
                        "{%0,%1,%2,%3}, {%4,%5,%6,%7}, {%8,%9}, {%0,%1,%2,%3};\n"
                        : "+f"(acc[mt][ntile][0]), "+f"(acc[mt][ntile][1]),
                          "+f"(acc[mt][ntile][2]), "+f"(acc[mt][ntile][3])
                        : "r"(a[mt][0]), "r"(a[mt][1]), "r"(a[mt][2]), "r"(a[mt][3]),
                          "r"(b[ntile][0]), "r"(b[ntile][1]));
                }
        }
        if (more) {
#pragma unroll
            for (int r = 0; r < 2; r++) {
                uint4 ua = { f2tf(pa[r].x), f2tf(pa[r].y), f2tf(pa[r].z), f2tf(pa[r].w) };
                *(uint4*)&As[nxt][lrow + r * 64][lcol] = ua;
                uint4 ub = { f2tf(pb[r].x), f2tf(pb[r].y), f2tf(pb[r].z), f2tf(pb[r].w) };
                *(uint4*)&Bs[nxt][lrow + r * 64][lcol] = ub;
            }
        }
        __syncthreads();
    }

    // epilogue
    const int gc2 = (lane & 3) * 2;
#pragma unroll
    for (int mt = 0; mt < 2; mt++) {
        long row0 = bm + wm * 32 + mt * 16 + gr;
#pragma unroll
        for (int ntile = 0; ntile < 8; ntile++) {
            int col = bn + wn * 64 + ntile * 8 + gc2;
            float b0 = bias ? bias[col] : 0.f;
            float b1 = bias ? bias[col + 1] : 0.f;
            float2 v0, v1;
            v0.x = acc[mt][ntile][0] + b0; v0.y = acc[mt][ntile][1] + b1;
            v1.x = acc[mt][ntile][2] + b0; v1.y = acc[mt][ntile][3] + b1;
            if (act == 1) {
                v0.x = softplusf(v0.x); v0.y = softplusf(v0.y);
                v1.x = softplusf(v1.x); v1.y = softplusf(v1.y);
            }
            *(float2*)(C + row0 * N + col)       = v0;
            *(float2*)(C + (row0 + 8) * N + col) = v1;
        }
    }
}

// ---------------- orchestration ----------------
extern "C" void kernel_launch(void* const* d_in, const int* in_sizes, int n_in,
                              void* d_out, int out_size)
{
    const float* X      = (const float*)d_in[0];
    const int*   adj    = (const int*)  d_in[1];
    const float* W_ih_c = (const float*)d_in[2];
    const float* W_hh_c = (const float*)d_in[3];
    const float* b_ih_c = (const float*)d_in[4];
    const float* b_hh_c = (const float*)d_in[5];
    const float* W_ih_l = (const float*)d_in[6];
    const float* W_hh_l = (const float*)d_in[7];
    const float* b_ih_l = (const float*)d_in[8];
    const float* b_hh_l = (const float*)d_in[9];
    const float* W_ih_r = (const float*)d_in[10];
    const float* W_hh_r = (const float*)d_in[11];
    const float* b_ih_r = (const float*)d_in[12];
    const float* b_hh_r = (const float*)d_in[13];
    const float* Wg     = (const float*)d_in[14];
    const float* bg     = (const float*)d_in[15];
    const float* Wm     = (const float*)d_in[16];
    const float* Wmu    = (const float*)d_in[17];
    const float* bmu    = (const float*)d_in[18];
    const float* Wstd   = (const float*)d_in[19];
    const float* bstd   = (const float*)d_in[20];

    float *Hin, *Hv, *gh, *msg, *giAll, *Xpad, *Wx32, *Wmsg;
    cudaGetSymbolAddress((void**)&Hin,   g_Hin);
    cudaGetSymbolAddress((void**)&Hv,    g_Hv);
    cudaGetSymbolAddress((void**)&gh,    g_gh);
    cudaGetSymbolAddress((void**)&msg,   g_msg);
    cudaGetSymbolAddress((void**)&giAll, g_giAll);
    cudaGetSymbolAddress((void**)&Xpad,  g_Xpad);
    cudaGetSymbolAddress((void**)&Wx32,  g_Wx32);
    cudaGetSymbolAddress((void**)&Wmsg,  g_Wmsg);

    cudaMemsetAsync(Hin, 0, sizeof(float) * 7LL * BATCH * HDIM, 0);

    pack_xpad<<<(13 * BATCH * 32) / 256, 256>>>(X, adj, Xpad);
    pack_wx32<<<(G3 * 32) / 256, 256>>>(W_ih_c, Wx32,               27);
    pack_wx32<<<(G3 * 32) / 256, 256>>>(W_ih_l, Wx32 + (long)G3*32, 27);
    pack_wx32<<<(G3 * 32) / 256, 256>>>(W_ih_r, Wx32 + 2L*G3*32,    23);
    pack_msgw<<<(NMSG * HDIM) / 256, 256>>>(Wg, Wm, Wmsg);

    // precompute all gi's: 3 GEMMs over the packed X (K=32)
    const long SEG = 6LL * BATCH;   // rows per c/l segment
    dim3 gGI6(G3 / BN, (6 * BATCH) / BM);   // (24, 96)
    dim3 gGI1(G3 / BN, BATCH / BM);         // (24, 16)
    tgemm_nt<<<gGI6, 256>>>(Xpad,                 Wx32,               b_ih_c,
                            giAll,                G3, 32, 0);
    tgemm_nt<<<gGI6, 256>>>(Xpad + SEG * 32,      Wx32 + (long)G3*32, b_ih_l,
                            giAll + SEG * G3,     G3, 32, 0);
    tgemm_nt<<<gGI1, 256>>>(Xpad + 2 * SEG * 32,  Wx32 + 2L*G3*32,    b_ih_r,
                            giAll + 2 * SEG * G3, G3, 32, 0);

    dim3 gGH(G3 / BN, BATCH / BM);             // (24, 16)
    dim3 gMS(NMSG / BN, BATCH / BM);           // (32, 16)
    dim3 gOUT(256 / BN, BATCH / BM);           // (2, 16)
    const int EW = (BATCH * HDIM) / 256;       // 8192

    for (int v = 6; v >= 0; v--) {
        float* Hin_v = Hin + (long)v * BATCH * HDIM;
        const float* Whh  = (v == 0) ? W_hh_r : W_hh_c;
        const float* bhh  = (v == 0) ? b_hh_r : b_hh_c;
        const float* gi1  = (v == 0) ? (giAll + 2 * SEG * G3)
                                     : (giAll + (long)(v - 1) * BATCH * G3);

        // GRU 1
        tgemm_nt<<<gGH, 256>>>(Hin_v, Whh, bhh, gh, G3, HDIM, 0);
        gru_combine<<<EW, 256>>>(gi1, gh, Hin_v, Hv);

        if (v > 0) {
            // GRU 2 (self-loop)
            const float* gi2 = giAll + (SEG + (long)(v - 1) * BATCH) * G3;
            tgemm_nt<<<gGH, 256>>>(Hv, W_hh_l, b_hh_l, gh, G3, HDIM, 0);
            gru_combine<<<EW, 256>>>(gi2, gh, Hv, Hv);

            // sender projections A|B|C|D, then push to all receivers u < v
            tgemm_nt<<<gMS, 256>>>(Hv, Wmsg, nullptr, msg, NMSG, HDIM, 0);
            msg_scatter_all<<<EW, 256>>>(msg, adj, bg, Hin, v);
        }
    }

    float* out = (float*)d_out;
    tgemm_nt<<<gOUT, 256>>>(Hv, Wmu,  bmu,  out,               256, HDIM, 0);
    tgemm_nt<<<gOUT, 256>>>(Hv, Wstd, bstd, out + BATCH * 256, 256, HDIM, 1);
}